// round 7
// baseline (speedup 1.0000x reference)
#include <cuda_runtime.h>
#include <cuda_bf16.h>

#define BN 256
#define TN 2048
#define HN 64
#define GN 192   /* 3*H */
#define MB 4     /* batches per scan block */

// ---------------------------------------------------------------------------
// Scratch (no allocation allowed -> __device__ globals)
// NOTE: scan prefetch deliberately over/under-runs one row past its direction
// slab; layout [2][...] keeps those accesses inside this object.
// ---------------------------------------------------------------------------
__device__ float g_gx[2][(size_t)BN * TN * GN];        // per-direction input gates
__device__ float g_out0[(size_t)BN * TN * 2 * HN];     // layer-0 output [B*T, 128]
__device__ float g_emb[BN * 2 * HN];                   // layer-1 final states [B, 128]

__device__ __forceinline__ float sigf(float x) {
    return __fdividef(1.f, 1.f + __expf(-x));
}
__device__ __forceinline__ float tanhfast(float x) {
    x = fminf(fmaxf(x, -15.f), 15.f);
    float e = __expf(-2.f * x);
    return __fdividef(1.f - e, 1.f + e);
}

// Packed fp32x2 helpers (Blackwell dual-rate fp32 path)
#define FFMA2(acc, a, b) \
    asm("fma.rn.f32x2 %0, %1, %2, %0;" : "+l"(acc) : "l"(a), "l"(b))

__device__ __forceinline__ unsigned long long packdup(float v) {
    unsigned long long r;
    asm("mov.b64 %0, {%1, %1};" : "=l"(r) : "f"(v));
    return r;
}
__device__ __forceinline__ float2 unpack2(unsigned long long p) {
    float2 f;
    asm("mov.b64 {%0, %1}, %2;" : "=f"(f.x), "=f"(f.y) : "l"(p));
    return f;
}

// ---------------------------------------------------------------------------
// Input-gate GEMM: gx[row, g] = bih[g] + sum_i in[row, i] * Wih[g, i]
// 64 rows/block, 192 threads (one gate each), K chunked by 32 via smem.
// ---------------------------------------------------------------------------
template <int IN>
__global__ __launch_bounds__(192) void gx_kernel(
    const float* __restrict__ xin, int use_out0,
    const float* __restrict__ Wf, const float* __restrict__ bf,
    const float* __restrict__ Wb, const float* __restrict__ bb)
{
    const int dir = blockIdx.y;
    const float* __restrict__ W    = dir ? Wb : Wf;
    const float* __restrict__ bias = dir ? bb : bf;
    const float* __restrict__ in   = use_out0 ? g_out0 : xin;
    float* __restrict__ gx = g_gx[dir];
    const int tid = threadIdx.x;
    const long rowbase = (long)blockIdx.x * 64;

    __shared__ float Wsh[32 * 193];   // [i][g]
    __shared__ float xsh[32 * 68];    // [i][r], 16B-aligned rows

    unsigned long long acc2[32];      // 32 packed pairs = 64 row accumulators
#pragma unroll
    for (int rv = 0; rv < 32; rv++) acc2[rv] = 0ull;

#pragma unroll
    for (int kc = 0; kc < IN; kc += 32) {
        const int kw = (IN - kc < 32) ? (IN - kc) : 32;
        for (int idx = tid; idx < kw * 192; idx += 192) {
            int g = idx / kw, i = idx - g * kw;
            Wsh[i * 193 + g] = W[(long)g * IN + kc + i];
        }
        for (int idx = tid; idx < kw * 64; idx += 192) {
            int r = idx / kw, i = idx - r * kw;
            xsh[i * 68 + r] = in[(rowbase + r) * IN + kc + i];
        }
        __syncthreads();
        for (int i = 0; i < kw; i++) {
            const unsigned long long w2 = packdup(Wsh[i * 193 + tid]);
            const ulonglong2* x2 = (const ulonglong2*)&xsh[i * 68];
#pragma unroll
            for (int rv = 0; rv < 16; rv++) {
                ulonglong2 xv = x2[rv];
                FFMA2(acc2[2 * rv + 0], w2, xv.x);
                FFMA2(acc2[2 * rv + 1], w2, xv.y);
            }
        }
        __syncthreads();
    }
    const float bv = bias[tid];
#pragma unroll 8
    for (int rv = 0; rv < 32; rv++) {
        float2 p = unpack2(acc2[rv]);
        gx[(rowbase + 2 * rv + 0) * GN + tid] = p.x + bv;
        gx[(rowbase + 2 * rv + 1) * GN + tid] = p.y + bv;
    }
}

// ---------------------------------------------------------------------------
// Recurrent scan, thread-per-(hidden-unit, batch): 256 threads, tid = hu*4+b.
// Each thread computes gates r,z,n for ITS (hu,b): no cross-thread pointwise,
// h_old kept in a register, ONE barrier per step (ping-pong h buffers).
// Weights: r,z rows in static smem (broadcast-dedup reads), n row in regs.
// gx loads prefetched one full step ahead.
// ---------------------------------------------------------------------------
__global__ __launch_bounds__(4 * HN, 1) void scan_kernel(
    int layer,
    const float* __restrict__ Whh_f, const float* __restrict__ bhh_f,
    const float* __restrict__ Whh_b, const float* __restrict__ bhh_b)
{
    const int dir = blockIdx.x & 1;
    const int blk = blockIdx.x >> 1;
    const int tid = threadIdx.x;
    const int hu  = tid >> 2;
    const int b   = tid & 3;
    const float* __restrict__ Whh = dir ? Whh_b : Whh_f;
    const float* __restrict__ bhh = dir ? bhh_b : bhh_f;
    const float* __restrict__ gx  = g_gx[dir];
    const int bbase  = blk * MB;
    const int dirOff = dir ? HN : 0;

    __shared__ float Wrz[2 * HN * HN];   // 32KB: r rows 0..63, z rows 64..127
    __shared__ float hbuf[2][MB][HN];    // ping-pong h state

    // stage r/z weight rows (layout identical to source -> linear copy)
    for (int idx = tid; idx < 2 * HN * HN; idx += 4 * HN)
        Wrz[idx] = Whh[idx];
    // n-gate row -> registers (64 floats = 32 packed pairs)
    ulonglong2 wn[16];
    {
        const ulonglong2* src = (const ulonglong2*)(Whh + (2 * HN + hu) * HN);
#pragma unroll
        for (int q = 0; q < 16; q++) wn[q] = src[q];
    }
    const float br = bhh[hu];
    const float bz = bhh[HN + hu];
    const float bn = bhh[2 * HN + hu];

    // zero both h buffers
    for (int idx = tid; idx < 2 * MB * HN; idx += 4 * HN)
        ((float*)hbuf)[idx] = 0.f;
    __syncthreads();

    // walking gx pointer for this (hu, b)
    const long stepoff = dir ? -(long)GN : (long)GN;
    const long t0 = dir ? (TN - 1) : 0;
    const float* gp = gx + ((long)(bbase + b) * TN + t0) * GN + hu;

    // preload step 0 gates
    float xr = __ldg(gp), xz = __ldg(gp + HN), xn = __ldg(gp + 2 * HN);
    gp += stepoff;

    float hreg = 0.f;
    float* __restrict__ seq = (layer == 0) ? g_out0 : nullptr;
    int p = 0;

    const ulonglong2* wr = (const ulonglong2*)(Wrz + hu * HN);
    const ulonglong2* wz = (const ulonglong2*)(Wrz + (HN + hu) * HN);

    for (int s = 0; s < TN; ++s) {
        const int t = dir ? (TN - 1 - s) : s;

        // prefetch step s+1 (safe over/under-run into adjacent g_gx slab)
        const float xr2 = __ldg(gp), xz2 = __ldg(gp + HN), xn2 = __ldg(gp + 2 * HN);
        gp += stepoff;

        // gate dot products over j (packed pairs, 6 independent chains)
        unsigned long long ar0 = 0ull, ar1 = 0ull;
        unsigned long long az0 = 0ull, az1 = 0ull;
        unsigned long long an0 = 0ull, an1 = 0ull;
        const ulonglong2* hv = (const ulonglong2*)hbuf[p][b];
#pragma unroll
        for (int q = 0; q < 16; q++) {
            const ulonglong2 hq = hv[q];
            const ulonglong2 wrq = wr[q];
            const ulonglong2 wzq = wz[q];
            FFMA2(ar0, wrq.x, hq.x); FFMA2(ar1, wrq.y, hq.y);
            FFMA2(az0, wzq.x, hq.x); FFMA2(az1, wzq.y, hq.y);
            FFMA2(an0, wn[q].x, hq.x); FFMA2(an1, wn[q].y, hq.y);
        }
        float2 pr0 = unpack2(ar0), pr1 = unpack2(ar1);
        float2 pz0 = unpack2(az0), pz1 = unpack2(az1);
        float2 pn0 = unpack2(an0), pn1 = unpack2(an1);
        const float ghr = br + ((pr0.x + pr0.y) + (pr1.x + pr1.y));
        const float ghz = bz + ((pz0.x + pz0.y) + (pz1.x + pz1.y));
        const float ghn = bn + ((pn0.x + pn0.y) + (pn1.x + pn1.y));

        // pointwise (fully thread-local)
        const float r = sigf(xr + ghr);
        const float z = sigf(xz + ghz);
        const float n = tanhfast(xn + r * ghn);
        hreg = n + z * (hreg - n);

        hbuf[p ^ 1][b][hu] = hreg;
        if (seq)
            seq[((long)(bbase + b) * TN + t) * (2 * HN) + dirOff + hu] = hreg;

        xr = xr2; xz = xz2; xn = xn2;
        p ^= 1;
        __syncthreads();
    }

    if (layer == 1)
        g_emb[(bbase + b) * (2 * HN) + dirOff + hu] = hreg;
}

// ---------------------------------------------------------------------------
// Head: LayerNorm(128) -> ReLU(W1) -> W2. One block per batch row.
// ---------------------------------------------------------------------------
__global__ __launch_bounds__(128) void head_kernel(
    const float* __restrict__ ln_g, const float* __restrict__ ln_b,
    const float* __restrict__ W1, const float* __restrict__ b1,
    const float* __restrict__ W2, const float* __restrict__ b2,
    float* __restrict__ out)
{
    const int b = blockIdx.x, tid = threadIdx.x;
    __shared__ float ysh[128], hsh[64], red[8];

    const float e = g_emb[b * 128 + tid];
    float s = e, q = e * e;
#pragma unroll
    for (int o = 16; o > 0; o >>= 1) {
        s += __shfl_down_sync(~0u, s, o);
        q += __shfl_down_sync(~0u, q, o);
    }
    if ((tid & 31) == 0) { red[tid >> 5] = s; red[4 + (tid >> 5)] = q; }
    __syncthreads();
    const float ssum = red[0] + red[1] + red[2] + red[3];
    const float qsum = red[4] + red[5] + red[6] + red[7];
    const float mu = ssum * (1.f / 128.f);
    const float var = qsum * (1.f / 128.f) - mu * mu;
    ysh[tid] = (e - mu) * rsqrtf(var + 1e-5f) * ln_g[tid] + ln_b[tid];
    __syncthreads();
    if (tid < 64) {
        float a = b1[tid];
#pragma unroll 8
        for (int i = 0; i < 128; i++) a += ysh[i] * W1[tid * 128 + i];
        hsh[tid] = fmaxf(a, 0.f);
    }
    __syncthreads();
    if (tid < 11) {
        float a = b2[tid];
#pragma unroll
        for (int i = 0; i < 64; i++) a += hsh[i] * W2[tid * 64 + i];
        out[b * 11 + tid] = a;
    }
}

// ---------------------------------------------------------------------------
extern "C" void kernel_launch(void* const* d_in, const int* in_sizes, int n_in,
                              void* d_out, int out_size)
{
    const float* x     = (const float*)d_in[0];
    const float* Wih00 = (const float*)d_in[1];
    const float* Whh00 = (const float*)d_in[2];
    const float* bih00 = (const float*)d_in[3];
    const float* bhh00 = (const float*)d_in[4];
    const float* Wih01 = (const float*)d_in[5];
    const float* Whh01 = (const float*)d_in[6];
    const float* bih01 = (const float*)d_in[7];
    const float* bhh01 = (const float*)d_in[8];
    const float* Wih10 = (const float*)d_in[9];
    const float* Whh10 = (const float*)d_in[10];
    const float* bih10 = (const float*)d_in[11];
    const float* bhh10 = (const float*)d_in[12];
    const float* Wih11 = (const float*)d_in[13];
    const float* Whh11 = (const float*)d_in[14];
    const float* bih11 = (const float*)d_in[15];
    const float* bhh11 = (const float*)d_in[16];
    const float* ln_g  = (const float*)d_in[17];
    const float* ln_b  = (const float*)d_in[18];
    const float* W1    = (const float*)d_in[19];
    const float* b1    = (const float*)d_in[20];
    const float* W2    = (const float*)d_in[21];
    const float* b2    = (const float*)d_in[22];
    float* out = (float*)d_out;

    const dim3 gxGrid(BN * TN / 64, 2);
    const int scBlocks = (BN / MB) * 2;   // dir folded into blockIdx.x

    // Layer 0: input gates from x (IN=29), then bidirectional scan -> g_out0
    gx_kernel<29><<<gxGrid, 192>>>(x, 0, Wih00, bih00, Wih01, bih01);
    scan_kernel<<<scBlocks, 4 * HN>>>(0, Whh00, bhh00, Whh01, bhh01);

    // Layer 1: input gates from g_out0 (IN=128), then scan -> g_emb
    gx_kernel<128><<<gxGrid, 192>>>(x, 1, Wih10, bih10, Wih11, bih11);
    scan_kernel<<<scBlocks, 4 * HN>>>(1, Whh10, bhh10, Whh11, bhh11);

    // Head
    head_kernel<<<BN, 128>>>(ln_g, ln_b, W1, b1, W2, b2, out);
}

// round 10
// speedup vs baseline: 1.2698x; 1.2698x over previous
#include <cuda_runtime.h>
#include <cuda_bf16.h>

#define BN 256
#define TN 2048
#define HN 64
#define GN 192   /* 3*H */
#define MB 4     /* batches per scan block */

// ---------------------------------------------------------------------------
// Scratch (no allocation allowed -> __device__ globals)
// NOTE: scan prefetch (distance 2) deliberately over/under-runs up to two rows
// past its direction slab; layout [2][...] keeps those accesses inside this
// single object for both directions at both edges.
// ---------------------------------------------------------------------------
__device__ float g_gx[2][(size_t)BN * TN * GN];        // per-direction input gates
__device__ float g_out0[(size_t)BN * TN * 2 * HN];     // layer-0 output [B*T, 128]
__device__ float g_emb[BN * 2 * HN];                   // layer-1 final states [B, 128]

__device__ __forceinline__ float sigf(float x) {
    return __fdividef(1.f, 1.f + __expf(-x));
}
__device__ __forceinline__ float tanhfast(float x) {
    x = fminf(fmaxf(x, -15.f), 15.f);
    float e = __expf(-2.f * x);
    return __fdividef(1.f - e, 1.f + e);
}

// Packed fp32x2 helpers (Blackwell dual-rate fp32 path)
#define FFMA2(acc, a, b) \
    asm("fma.rn.f32x2 %0, %1, %2, %0;" : "+l"(acc) : "l"(a), "l"(b))

__device__ __forceinline__ unsigned long long packdup(float v) {
    unsigned long long r;
    asm("mov.b64 %0, {%1, %1};" : "=l"(r) : "f"(v));
    return r;
}
__device__ __forceinline__ float2 unpack2(unsigned long long p) {
    float2 f;
    asm("mov.b64 {%0, %1}, %2;" : "=f"(f.x), "=f"(f.y) : "l"(p));
    return f;
}

// ---------------------------------------------------------------------------
// Input-gate GEMM: gx[row, g] = bih[g] + sum_i in[row, i] * Wih[g, i]
// 64 rows/block, 192 threads (one gate each), K chunked by 32 via smem.
// ---------------------------------------------------------------------------
template <int IN>
__global__ __launch_bounds__(192) void gx_kernel(
    const float* __restrict__ xin, int use_out0,
    const float* __restrict__ Wf, const float* __restrict__ bf,
    const float* __restrict__ Wb, const float* __restrict__ bb)
{
    const int dir = blockIdx.y;
    const float* __restrict__ W    = dir ? Wb : Wf;
    const float* __restrict__ bias = dir ? bb : bf;
    const float* __restrict__ in   = use_out0 ? g_out0 : xin;
    float* __restrict__ gx = g_gx[dir];
    const int tid = threadIdx.x;
    const long rowbase = (long)blockIdx.x * 64;

    __shared__ float Wsh[32 * 193];   // [i][g]
    __shared__ float xsh[32 * 68];    // [i][r], 16B-aligned rows

    unsigned long long acc2[32];      // 32 packed pairs = 64 row accumulators
#pragma unroll
    for (int rv = 0; rv < 32; rv++) acc2[rv] = 0ull;

#pragma unroll
    for (int kc = 0; kc < IN; kc += 32) {
        const int kw = (IN - kc < 32) ? (IN - kc) : 32;
        for (int idx = tid; idx < kw * 192; idx += 192) {
            int g = idx / kw, i = idx - g * kw;
            Wsh[i * 193 + g] = W[(long)g * IN + kc + i];
        }
        for (int idx = tid; idx < kw * 64; idx += 192) {
            int r = idx / kw, i = idx - r * kw;
            xsh[i * 68 + r] = in[(rowbase + r) * IN + kc + i];
        }
        __syncthreads();
        for (int i = 0; i < kw; i++) {
            const unsigned long long w2 = packdup(Wsh[i * 193 + tid]);
            const ulonglong2* x2 = (const ulonglong2*)&xsh[i * 68];
#pragma unroll
            for (int rv = 0; rv < 16; rv++) {
                ulonglong2 xv = x2[rv];
                FFMA2(acc2[2 * rv + 0], w2, xv.x);
                FFMA2(acc2[2 * rv + 1], w2, xv.y);
            }
        }
        __syncthreads();
    }
    const float bv = bias[tid];
#pragma unroll 8
    for (int rv = 0; rv < 32; rv++) {
        float2 p = unpack2(acc2[rv]);
        gx[(rowbase + 2 * rv + 0) * GN + tid] = p.x + bv;
        gx[(rowbase + 2 * rv + 1) * GN + tid] = p.y + bv;
    }
}

// ---------------------------------------------------------------------------
// Recurrent scan, thread-per-(hidden-unit, batch): 256 threads, tid = hu*4+b.
// ALL THREE weight rows (r,z,n for this hu) in registers, j-paired packed:
// 64 floats/row = SIXTEEN ulonglong2 per gate (4 floats each) -> 192 regs of
// weights; __launch_bounds__(256,1) grants up to 255 so they stay resident.
// h state in smem ping-pong (one barrier per step), h_old in a register,
// pointwise fully thread-local. gx prefetched TWO steps ahead.
// ---------------------------------------------------------------------------
__global__ __launch_bounds__(4 * HN, 1) void scan_kernel(
    int layer,
    const float* __restrict__ Whh_f, const float* __restrict__ bhh_f,
    const float* __restrict__ Whh_b, const float* __restrict__ bhh_b)
{
    const int dir = blockIdx.x & 1;
    const int blk = blockIdx.x >> 1;
    const int tid = threadIdx.x;
    const int hu  = tid >> 2;
    const int b   = tid & 3;
    const float* __restrict__ Whh = dir ? Whh_b : Whh_f;
    const float* __restrict__ bhh = dir ? bhh_b : bhh_f;
    const float* __restrict__ gx  = g_gx[dir];
    const int bbase  = blk * MB;
    const int dirOff = dir ? HN : 0;

    __shared__ __align__(16) float hbuf[2][MB][HN];   // ping-pong h state

    // weight rows -> registers, j-paired packed (16 x ulonglong2 = 64 floats)
    ulonglong2 wr[16], wz[16], wn[16];
    {
        const ulonglong2* rsrc = (const ulonglong2*)(Whh + hu * HN);
        const ulonglong2* zsrc = (const ulonglong2*)(Whh + (HN + hu) * HN);
        const ulonglong2* nsrc = (const ulonglong2*)(Whh + (2 * HN + hu) * HN);
#pragma unroll
        for (int q = 0; q < 16; q++) { wr[q] = rsrc[q]; wz[q] = zsrc[q]; wn[q] = nsrc[q]; }
    }
    const float br = bhh[hu];
    const float bz = bhh[HN + hu];
    const float bn = bhh[2 * HN + hu];

    // zero both h buffers
    for (int idx = tid; idx < 2 * MB * HN; idx += 4 * HN)
        ((float*)hbuf)[idx] = 0.f;
    __syncthreads();

    // walking gx pointer for this (hu, b)
    const long stepoff = dir ? -(long)GN : (long)GN;
    const long t0 = dir ? (TN - 1) : 0;
    const float* gp = gx + ((long)(bbase + b) * TN + t0) * GN + hu;

    // preload steps 0 and 1 (distance-2 pipeline)
    float xr0 = __ldg(gp), xz0 = __ldg(gp + HN), xn0 = __ldg(gp + 2 * HN);
    gp += stepoff;
    float xr1 = __ldg(gp), xz1 = __ldg(gp + HN), xn1 = __ldg(gp + 2 * HN);
    gp += stepoff;

    float hreg = 0.f;
    float* __restrict__ seq = (layer == 0) ? g_out0 : nullptr;
    int p = 0;

    for (int s = 0; s < TN; ++s) {
        const int t = dir ? (TN - 1 - s) : s;

        // prefetch step s+2 (over/under-run <= 2 rows, stays inside g_gx)
        const float xr2 = __ldg(gp), xz2 = __ldg(gp + HN), xn2 = __ldg(gp + 2 * HN);
        gp += stepoff;

        // three gate dot products over ALL 64 j (16 quads), two chains each
        unsigned long long ar0 = 0ull, ar1 = 0ull;
        unsigned long long az0 = 0ull, az1 = 0ull;
        unsigned long long an0 = 0ull, an1 = 0ull;
        const ulonglong2* hv = (const ulonglong2*)hbuf[p][b];
#pragma unroll
        for (int q = 0; q < 16; q++) {
            const ulonglong2 hq = hv[q];      // LDS.128, 4-way broadcast
            FFMA2(ar0, wr[q].x, hq.x); FFMA2(ar1, wr[q].y, hq.y);
            FFMA2(az0, wz[q].x, hq.x); FFMA2(az1, wz[q].y, hq.y);
            FFMA2(an0, wn[q].x, hq.x); FFMA2(an1, wn[q].y, hq.y);
        }
        float2 pr0 = unpack2(ar0), pr1 = unpack2(ar1);
        float2 pz0 = unpack2(az0), pz1 = unpack2(az1);
        float2 pn0 = unpack2(an0), pn1 = unpack2(an1);
        const float ghr = br + ((pr0.x + pr0.y) + (pr1.x + pr1.y));
        const float ghz = bz + ((pz0.x + pz0.y) + (pz1.x + pz1.y));
        const float ghn = bn + ((pn0.x + pn0.y) + (pn1.x + pn1.y));

        // pointwise (fully thread-local)
        const float r = sigf(xr0 + ghr);
        const float z = sigf(xz0 + ghz);
        const float n = tanhfast(xn0 + r * ghn);
        hreg = n + z * (hreg - n);

        hbuf[p ^ 1][b][hu] = hreg;
        if (seq)
            seq[((long)(bbase + b) * TN + t) * (2 * HN) + dirOff + hu] = hreg;

        xr0 = xr1; xz0 = xz1; xn0 = xn1;
        xr1 = xr2; xz1 = xz2; xn1 = xn2;
        p ^= 1;
        __syncthreads();
    }

    if (layer == 1)
        g_emb[(bbase + b) * (2 * HN) + dirOff + hu] = hreg;
}

// ---------------------------------------------------------------------------
// Head: LayerNorm(128) -> ReLU(W1) -> W2. One block per batch row.
// ---------------------------------------------------------------------------
__global__ __launch_bounds__(128) void head_kernel(
    const float* __restrict__ ln_g, const float* __restrict__ ln_b,
    const float* __restrict__ W1, const float* __restrict__ b1,
    const float* __restrict__ W2, const float* __restrict__ b2,
    float* __restrict__ out)
{
    const int b = blockIdx.x, tid = threadIdx.x;
    __shared__ float ysh[128], hsh[64], red[8];

    const float e = g_emb[b * 128 + tid];
    float s = e, q = e * e;
#pragma unroll
    for (int o = 16; o > 0; o >>= 1) {
        s += __shfl_down_sync(~0u, s, o);
        q += __shfl_down_sync(~0u, q, o);
    }
    if ((tid & 31) == 0) { red[tid >> 5] = s; red[4 + (tid >> 5)] = q; }
    __syncthreads();
    const float ssum = red[0] + red[1] + red[2] + red[3];
    const float qsum = red[4] + red[5] + red[6] + red[7];
    const float mu = ssum * (1.f / 128.f);
    const float var = qsum * (1.f / 128.f) - mu * mu;
    ysh[tid] = (e - mu) * rsqrtf(var + 1e-5f) * ln_g[tid] + ln_b[tid];
    __syncthreads();
    if (tid < 64) {
        float a = b1[tid];
#pragma unroll 8
        for (int i = 0; i < 128; i++) a += ysh[i] * W1[tid * 128 + i];
        hsh[tid] = fmaxf(a, 0.f);
    }
    __syncthreads();
    if (tid < 11) {
        float a = b2[tid];
#pragma unroll
        for (int i = 0; i < 64; i++) a += hsh[i] * W2[tid * 64 + i];
        out[b * 11 + tid] = a;
    }
}

// ---------------------------------------------------------------------------
extern "C" void kernel_launch(void* const* d_in, const int* in_sizes, int n_in,
                              void* d_out, int out_size)
{
    const float* x     = (const float*)d_in[0];
    const float* Wih00 = (const float*)d_in[1];
    const float* Whh00 = (const float*)d_in[2];
    const float* bih00 = (const float*)d_in[3];
    const float* bhh00 = (const float*)d_in[4];
    const float* Wih01 = (const float*)d_in[5];
    const float* Whh01 = (const float*)d_in[6];
    const float* bih01 = (const float*)d_in[7];
    const float* bhh01 = (const float*)d_in[8];
    const float* Wih10 = (const float*)d_in[9];
    const float* Whh10 = (const float*)d_in[10];
    const float* bih10 = (const float*)d_in[11];
    const float* bhh10 = (const float*)d_in[12];
    const float* Wih11 = (const float*)d_in[13];
    const float* Whh11 = (const float*)d_in[14];
    const float* bih11 = (const float*)d_in[15];
    const float* bhh11 = (const float*)d_in[16];
    const float* ln_g  = (const float*)d_in[17];
    const float* ln_b  = (const float*)d_in[18];
    const float* W1    = (const float*)d_in[19];
    const float* b1    = (const float*)d_in[20];
    const float* W2    = (const float*)d_in[21];
    const float* b2    = (const float*)d_in[22];
    float* out = (float*)d_out;

    const dim3 gxGrid(BN * TN / 64, 2);
    const int scBlocks = (BN / MB) * 2;   // dir folded into blockIdx.x

    // Layer 0: input gates from x (IN=29), then bidirectional scan -> g_out0
    gx_kernel<29><<<gxGrid, 192>>>(x, 0, Wih00, bih00, Wih01, bih01);
    scan_kernel<<<scBlocks, 4 * HN>>>(0, Whh00, bhh00, Whh01, bhh01);

    // Layer 1: input gates from g_out0 (IN=128), then scan -> g_emb
    gx_kernel<128><<<gxGrid, 192>>>(x, 1, Wih10, bih10, Wih11, bih11);
    scan_kernel<<<scBlocks, 4 * HN>>>(1, Whh10, bhh10, Whh11, bhh11);

    // Head
    head_kernel<<<BN, 128>>>(ln_g, ln_b, W1, b1, W2, b2, out);
}

// round 12
// speedup vs baseline: 1.6448x; 1.2953x over previous
#include <cuda_runtime.h>
#include <cuda_bf16.h>

#define BN 256
#define TN 2048
#define HN 64
#define GN 192   /* 3*H */
#define MB 4     /* batches per scan block */

// ---------------------------------------------------------------------------
// Scratch (no allocation allowed -> __device__ globals)
// NOTE: scan prefetch deliberately over/under-runs one row past its direction
// slab; layout [2][...] keeps those accesses inside this object.
// ---------------------------------------------------------------------------
__device__ float g_gx[2][(size_t)BN * TN * GN];        // per-direction input gates
__device__ float g_out0[(size_t)BN * TN * 2 * HN];     // layer-0 output [B*T, 128]
__device__ float g_emb[BN * 2 * HN];                   // layer-1 final states [B, 128]

__device__ __forceinline__ float sigf(float x) {
    return __fdividef(1.f, 1.f + __expf(-x));
}
__device__ __forceinline__ float tanhfast(float x) {
    x = fminf(fmaxf(x, -15.f), 15.f);
    float e = __expf(-2.f * x);
    return __fdividef(1.f - e, 1.f + e);
}

// Packed fp32x2 helpers (Blackwell dual-rate fp32 path)
#define FFMA2(acc, a, b) \
    asm("fma.rn.f32x2 %0, %1, %2, %0;" : "+l"(acc) : "l"(a), "l"(b))

__device__ __forceinline__ unsigned long long packdup(float v) {
    unsigned long long r;
    asm("mov.b64 %0, {%1, %1};" : "=l"(r) : "f"(v));
    return r;
}
__device__ __forceinline__ float2 unpack2(unsigned long long p) {
    float2 f;
    asm("mov.b64 {%0, %1}, %2;" : "=f"(f.x), "=f"(f.y) : "l"(p));
    return f;
}

// ---------------------------------------------------------------------------
// Input-gate GEMM: gx[row, g] = bih[g] + sum_i in[row, i] * Wih[g, i]
// 64 rows/block, 192 threads (one gate each), K chunked by 32 via smem.
// ---------------------------------------------------------------------------
template <int IN>
__global__ __launch_bounds__(192) void gx_kernel(
    const float* __restrict__ xin, int use_out0,
    const float* __restrict__ Wf, const float* __restrict__ bf,
    const float* __restrict__ Wb, const float* __restrict__ bb)
{
    const int dir = blockIdx.y;
    const float* __restrict__ W    = dir ? Wb : Wf;
    const float* __restrict__ bias = dir ? bb : bf;
    const float* __restrict__ in   = use_out0 ? g_out0 : xin;
    float* __restrict__ gx = g_gx[dir];
    const int tid = threadIdx.x;
    const long rowbase = (long)blockIdx.x * 64;

    __shared__ float Wsh[32 * 193];   // [i][g]
    __shared__ float xsh[32 * 68];    // [i][r], 16B-aligned rows

    unsigned long long acc2[32];      // 32 packed pairs = 64 row accumulators
#pragma unroll
    for (int rv = 0; rv < 32; rv++) acc2[rv] = 0ull;

#pragma unroll
    for (int kc = 0; kc < IN; kc += 32) {
        const int kw = (IN - kc < 32) ? (IN - kc) : 32;
        for (int idx = tid; idx < kw * 192; idx += 192) {
            int g = idx / kw, i = idx - g * kw;
            Wsh[i * 193 + g] = W[(long)g * IN + kc + i];
        }
        for (int idx = tid; idx < kw * 64; idx += 192) {
            int r = idx / kw, i = idx - r * kw;
            xsh[i * 68 + r] = in[(rowbase + r) * IN + kc + i];
        }
        __syncthreads();
        for (int i = 0; i < kw; i++) {
            const unsigned long long w2 = packdup(Wsh[i * 193 + tid]);
            const ulonglong2* x2 = (const ulonglong2*)&xsh[i * 68];
#pragma unroll
            for (int rv = 0; rv < 16; rv++) {
                ulonglong2 xv = x2[rv];
                FFMA2(acc2[2 * rv + 0], w2, xv.x);
                FFMA2(acc2[2 * rv + 1], w2, xv.y);
            }
        }
        __syncthreads();
    }
    const float bv = bias[tid];
#pragma unroll 8
    for (int rv = 0; rv < 32; rv++) {
        float2 p = unpack2(acc2[rv]);
        gx[(rowbase + 2 * rv + 0) * GN + tid] = p.x + bv;
        gx[(rowbase + 2 * rv + 1) * GN + tid] = p.y + bv;
    }
}

// ---------------------------------------------------------------------------
// Recurrent scan (the proven R5 structure). 192 threads = one per gate, MB=4
// batches per block. Whh row pre-duplicated into 64 packed f32x2 registers
// (~128 regs of weights). __launch_bounds__(192, 1) forces min-blocks=1 so
// ptxas grants ~175 regs and the weights STAY IN REGISTERS (the R5 run of
// this exact structure was silently spilling at 94 regs).
// h kept in smem as float4 h[j] = (b0,b1,b2,b3): one LDS.128 feeds two FFMA2.
// gx loads prefetched one step ahead (register double buffer).
// ---------------------------------------------------------------------------
__global__ __launch_bounds__(192, 1) void scan_kernel(
    int layer,
    const float* __restrict__ Whh_f, const float* __restrict__ bhh_f,
    const float* __restrict__ Whh_b, const float* __restrict__ bhh_b)
{
    const int dir = blockIdx.x & 1;
    const int blk = blockIdx.x >> 1;
    const int tid = threadIdx.x;                 // gate id 0..191
    const float* __restrict__ Whh = dir ? Whh_b : Whh_f;
    const float bh = (dir ? bhh_b : bhh_f)[tid];
    const float* __restrict__ gx = g_gx[dir];
    const int bbase = blk * MB;
    const int dirOff = dir ? HN : 0;

    __shared__ float4 hsh4[HN];      // h[j] = (b0,b1,b2,b3)
    __shared__ float4 gh4[GN];       // hidden-gate pre-activations, per-gate 4 batches
    __shared__ float4 sx4[GN];       // input-gate values

    // Whh row -> packed duplicated registers (128 regs; 1 block/SM)
    unsigned long long w2[HN];
#pragma unroll
    for (int j = 0; j < HN; j++) w2[j] = packdup(Whh[tid * HN + j]);
    const unsigned long long bh2 = packdup(bh);

    if (tid < HN) hsh4[tid] = make_float4(0.f, 0.f, 0.f, 0.f);
    __syncthreads();

    // walking gx pointers per batch lane
    const float* gp[MB];
    const long stepoff = dir ? -(long)GN : (long)GN;
    const long t0 = dir ? (TN - 1) : 0;
#pragma unroll
    for (int b = 0; b < MB; b++)
        gp[b] = gx + ((long)(bbase + b) * TN + t0) * GN + tid;

    // preload step 0
    float xg[MB];
#pragma unroll
    for (int b = 0; b < MB; b++) { xg[b] = __ldg(gp[b]); gp[b] += stepoff; }

    float* __restrict__ seq = (layer == 0) ? g_out0 : nullptr;

    for (int s = 0; s < TN; ++s) {
        const int t = dir ? (TN - 1 - s) : s;

        // prefetch step s+1 (pointer runs one row past the slab on the last
        // step; lands inside the adjacent g_gx direction slab -> in bounds)
        float xgn[MB];
#pragma unroll
        for (int b = 0; b < MB; b++) { xgn[b] = __ldg(gp[b]); gp[b] += stepoff; }

        unsigned long long acc01 = bh2, acc23 = bh2;
        const ulonglong2* h2 = (const ulonglong2*)hsh4;
#pragma unroll
        for (int j = 0; j < HN; j++) {
            ulonglong2 hv = h2[j];              // one LDS.128, broadcast
            FFMA2(acc01, w2[j], hv.x);
            FFMA2(acc23, w2[j], hv.y);
        }
        {
            float2 lo = unpack2(acc01), hi = unpack2(acc23);
            gh4[tid] = make_float4(lo.x, lo.y, hi.x, hi.y);
            sx4[tid] = make_float4(xg[0], xg[1], xg[2], xg[3]);
        }
#pragma unroll
        for (int b = 0; b < MB; b++) xg[b] = xgn[b];
        __syncthreads();

        // pointwise: item = hu*4 + b (conflict-free smem access pattern)
        const float* ghf = (const float*)gh4;
        const float* sxf = (const float*)sx4;
        float* hf = (float*)hsh4;
        for (int item = tid; item < MB * HN; item += 192) {
            const int hu = item >> 2, b = item & 3;
            const float r = sigf(sxf[hu * 4 + b] + ghf[hu * 4 + b]);
            const float z = sigf(sxf[(64 + hu) * 4 + b] + ghf[(64 + hu) * 4 + b]);
            const float n = tanhfast(sxf[(128 + hu) * 4 + b] + r * ghf[(128 + hu) * 4 + b]);
            const float hold = hf[item];
            const float hnew = n + z * (hold - n);
            hf[item] = hnew;
            if (seq)
                seq[((long)(bbase + b) * TN + t) * (2 * HN) + dirOff + hu] = hnew;
        }
        __syncthreads();
    }

    if (layer == 1) {
        const float* hf = (const float*)hsh4;
        for (int item = tid; item < MB * HN; item += 192) {
            const int hu = item >> 2, b = item & 3;
            g_emb[(bbase + b) * (2 * HN) + dirOff + hu] = hf[item];
        }
    }
}

// ---------------------------------------------------------------------------
// Head: LayerNorm(128) -> ReLU(W1) -> W2. One block per batch row.
// ---------------------------------------------------------------------------
__global__ __launch_bounds__(128) void head_kernel(
    const float* __restrict__ ln_g, const float* __restrict__ ln_b,
    const float* __restrict__ W1, const float* __restrict__ b1,
    const float* __restrict__ W2, const float* __restrict__ b2,
    float* __restrict__ out)
{
    const int b = blockIdx.x, tid = threadIdx.x;
    __shared__ float ysh[128], hsh[64], red[8];

    const float e = g_emb[b * 128 + tid];
    float s = e, q = e * e;
#pragma unroll
    for (int o = 16; o > 0; o >>= 1) {
        s += __shfl_down_sync(~0u, s, o);
        q += __shfl_down_sync(~0u, q, o);
    }
    if ((tid & 31) == 0) { red[tid >> 5] = s; red[4 + (tid >> 5)] = q; }
    __syncthreads();
    const float ssum = red[0] + red[1] + red[2] + red[3];
    const float qsum = red[4] + red[5] + red[6] + red[7];
    const float mu = ssum * (1.f / 128.f);
    const float var = qsum * (1.f / 128.f) - mu * mu;
    ysh[tid] = (e - mu) * rsqrtf(var + 1e-5f) * ln_g[tid] + ln_b[tid];
    __syncthreads();
    if (tid < 64) {
        float a = b1[tid];
#pragma unroll 8
        for (int i = 0; i < 128; i++) a += ysh[i] * W1[tid * 128 + i];
        hsh[tid] = fmaxf(a, 0.f);
    }
    __syncthreads();
    if (tid < 11) {
        float a = b2[tid];
#pragma unroll
        for (int i = 0; i < 64; i++) a += hsh[i] * W2[tid * 64 + i];
        out[b * 11 + tid] = a;
    }
}

// ---------------------------------------------------------------------------
extern "C" void kernel_launch(void* const* d_in, const int* in_sizes, int n_in,
                              void* d_out, int out_size)
{
    const float* x     = (const float*)d_in[0];
    const float* Wih00 = (const float*)d_in[1];
    const float* Whh00 = (const float*)d_in[2];
    const float* bih00 = (const float*)d_in[3];
    const float* bhh00 = (const float*)d_in[4];
    const float* Wih01 = (const float*)d_in[5];
    const float* Whh01 = (const float*)d_in[6];
    const float* bih01 = (const float*)d_in[7];
    const float* bhh01 = (const float*)d_in[8];
    const float* Wih10 = (const float*)d_in[9];
    const float* Whh10 = (const float*)d_in[10];
    const float* bih10 = (const float*)d_in[11];
    const float* bhh10 = (const float*)d_in[12];
    const float* Wih11 = (const float*)d_in[13];
    const float* Whh11 = (const float*)d_in[14];
    const float* bih11 = (const float*)d_in[15];
    const float* bhh11 = (const float*)d_in[16];
    const float* ln_g  = (const float*)d_in[17];
    const float* ln_b  = (const float*)d_in[18];
    const float* W1    = (const float*)d_in[19];
    const float* b1    = (const float*)d_in[20];
    const float* W2    = (const float*)d_in[21];
    const float* b2    = (const float*)d_in[22];
    float* out = (float*)d_out;

    const dim3 gxGrid(BN * TN / 64, 2);
    const int scBlocks = (BN / MB) * 2;   // dir folded into blockIdx.x

    // Layer 0: input gates from x (IN=29), then bidirectional scan -> g_out0
    gx_kernel<29><<<gxGrid, 192>>>(x, 0, Wih00, bih00, Wih01, bih01);
    scan_kernel<<<scBlocks, 192>>>(0, Whh00, bhh00, Whh01, bhh01);

    // Layer 1: input gates from g_out0 (IN=128), then scan -> g_emb
    gx_kernel<128><<<gxGrid, 192>>>(x, 1, Wih10, bih10, Wih11, bih11);
    scan_kernel<<<scBlocks, 192>>>(1, Whh10, bhh10, Whh11, bhh11);

    // Head
    head_kernel<<<BN, 128>>>(ln_g, ln_b, W1, b1, W2, b2, out);
}